// round 1
// baseline (speedup 1.0000x reference)
#include <cuda_runtime.h>
#include <cuda_bf16.h>

#define N_COLS   4096
#define N_TERMS  2048
#define COL4     (N_COLS / 4)      // 1024 float4 columns
#define ROW_BLOCKS 128
#define ROWS_PER   16              // 128 * 16 = 2048 >= 2047 reduced rows

// ---- scratch (no allocation allowed; device globals) ----
__device__ float  g_partial[ROW_BLOCKS * N_COLS];   // 2 MB partial |x| column sums
__device__ float4 g_scale[COL4];                    // per-column generator scale
__device__ float4 g_val[COL4];                      // per-column delta*0.5*crossf
__device__ int4   g_cross[COL4];                    // per-column crossing flag

// K1: partial column reduction of |x| over row chunks (rows 1..2047)
__global__ void k_abs_partial(const float* __restrict__ x) {
    int col4 = blockIdx.x * blockDim.x + threadIdx.x;   // 0..1023
    int rb   = blockIdx.y;
    int r0   = 1 + rb * ROWS_PER;
    int r1   = min(r0 + ROWS_PER, N_TERMS);
    const float4* x4 = (const float4*)x;
    float4 acc = make_float4(0.f, 0.f, 0.f, 0.f);
    #pragma unroll
    for (int r = 0; r < ROWS_PER; r++) {
        int row = r0 + r;
        if (row < r1) {
            float4 v = x4[(size_t)row * COL4 + col4];
            acc.x += fabsf(v.x);
            acc.y += fabsf(v.y);
            acc.z += fabsf(v.z);
            acc.w += fabsf(v.w);
        }
    }
    ((float4*)&g_partial[rb * N_COLS])[col4] = acc;
}

// K2: per-column stats: abs_sum -> lambda, scale, delta, cross; writes center row out[0]
__global__ void k_column_stats(const float* __restrict__ x, float* __restrict__ out) {
    int col = blockIdx.x * blockDim.x + threadIdx.x;    // 0..4095
    float s = 0.f;
    #pragma unroll 16
    for (int rb = 0; rb < ROW_BLOCKS; rb++)
        s += g_partial[rb * N_COLS + col];

    float c     = x[col];                 // x[0] center row
    float upper = c + s;
    float lower = c - s;
    float prod  = lower * upper;
    bool  cross = prod < 0.f;
    bool  pos   = lower >= 0.f;
    float crossf = cross ? 1.f : 0.f;
    float posf   = pos   ? 1.f : 0.f;

    float denom = upper - lower;
    float ratio = (denom != 0.f) ? (upper / denom) : 0.5f;
    float lam   = posf + crossf * ratio;

    float delta  = fmaxf(-lam * lower, (1.f - lam) * upper);
    float center = (delta * 0.5f + lam * c) * crossf + c * posf;

    ((float*)g_scale)[col] = lam * crossf + posf;
    ((float*)g_val)[col]   = delta * 0.5f * crossf;
    ((int*)g_cross)[col]   = cross ? 1 : 0;
    out[col] = center;
}

// K3: single-block exclusive prefix sum over 4096 cross flags + scatter delta/2
__global__ void k_scatter(float* __restrict__ out) {
    __shared__ int warp_sums[32];
    int t    = threadIdx.x;        // 0..1023, 4 columns each
    int lane = t & 31;
    int wid  = t >> 5;

    int4 cf = g_cross[t];
    int tsum = cf.x + cf.y + cf.z + cf.w;

    // inclusive warp scan of per-thread totals
    int v = tsum;
    #pragma unroll
    for (int o = 1; o < 32; o <<= 1) {
        int n = __shfl_up_sync(0xffffffffu, v, o);
        if (lane >= o) v += n;
    }
    if (lane == 31) warp_sums[wid] = v;
    __syncthreads();
    if (wid == 0) {
        int wv = warp_sums[lane];
        #pragma unroll
        for (int o = 1; o < 32; o <<= 1) {
            int n = __shfl_up_sync(0xffffffffu, wv, o);
            if (lane >= o) wv += n;
        }
        warp_sums[lane] = wv;
    }
    __syncthreads();

    int warp_off = (wid > 0) ? warp_sums[wid - 1] : 0;
    int excl = warp_off + (v - tsum);   // exclusive prefix for this thread's first column

    float4 val = g_val[t];
    int col = t * 4;
    int r = excl;
    if (cf.x) { out[(size_t)(N_TERMS + r) * N_COLS + col + 0] = val.x; r++; }
    if (cf.y) { out[(size_t)(N_TERMS + r) * N_COLS + col + 1] = val.y; r++; }
    if (cf.z) { out[(size_t)(N_TERMS + r) * N_COLS + col + 2] = val.z; r++; }
    if (cf.w) { out[(size_t)(N_TERMS + r) * N_COLS + col + 3] = val.w; }
}

// K4: gens: out[1:2048] = x[1:2048] * scale[col], float4 grid-stride
__global__ void k_gens(const float* __restrict__ x, float* __restrict__ out) {
    const float4* x4 = (const float4*)x;
    float4*       o4 = (float4*)out;
    const int total  = (N_TERMS - 1) * COL4;   // 2047 * 1024
    int stride = gridDim.x * blockDim.x;
    for (int i = blockIdx.x * blockDim.x + threadIdx.x; i < total; i += stride) {
        int j  = i + COL4;            // skip row 0
        int c4 = j & (COL4 - 1);
        float4 v = x4[j];
        float4 s = g_scale[c4];
        v.x *= s.x; v.y *= s.y; v.z *= s.z; v.w *= s.w;
        o4[j] = v;
    }
}

extern "C" void kernel_launch(void* const* d_in, const int* in_sizes, int n_in,
                              void* d_out, int out_size) {
    const float* x = (const float*)d_in[0];
    float* out     = (float*)d_out;

    // Zero the tail rows [2048, 6144) first (so x stays L2-warm between passes,
    // and the scatter in K3 lands on zeroed memory).
    cudaMemsetAsync(out + (size_t)N_TERMS * N_COLS, 0,
                    (size_t)N_COLS * N_COLS * sizeof(float), 0);

    dim3 g1(COL4 / 256, ROW_BLOCKS);           // (4, 128)
    k_abs_partial<<<g1, 256>>>(x);
    k_column_stats<<<N_COLS / 256, 256>>>(x, out);
    k_scatter<<<1, 1024>>>(out);
    k_gens<<<2048, 256>>>(x, out);
}

// round 2
// speedup vs baseline: 1.0314x; 1.0314x over previous
#include <cuda_runtime.h>
#include <cuda_bf16.h>

#define N_COLS   4096
#define N_TERMS  2048
#define COL4     (N_COLS / 4)      // 1024 float4 columns
#define ROW_BLOCKS 128
#define ROWS_PER   16              // 128 * 16 = 2048 >= 2047 reduced rows

// ---- scratch (no allocation allowed; device globals) ----
__device__ float  g_partial[ROW_BLOCKS * N_COLS];   // 2 MB partial |x| column sums
__device__ float4 g_scale[COL4];                    // per-column generator scale
__device__ float4 g_val[COL4];                      // per-column delta*0.5*crossf
__device__ int4   g_cross[COL4];                    // per-column crossing flag

// K1: partial column reduction of |x| over row chunks (rows 1..2047)
__global__ void k_abs_partial(const float* __restrict__ x) {
    int col4 = blockIdx.x * blockDim.x + threadIdx.x;   // 0..1023
    int rb   = blockIdx.y;
    int r0   = 1 + rb * ROWS_PER;
    const float4* x4 = (const float4*)x;
    float4 acc = make_float4(0.f, 0.f, 0.f, 0.f);
    #pragma unroll
    for (int r = 0; r < ROWS_PER; r++) {
        int row = r0 + r;
        if (row < N_TERMS) {
            float4 v = x4[(size_t)row * COL4 + col4];
            acc.x += fabsf(v.x);
            acc.y += fabsf(v.y);
            acc.z += fabsf(v.z);
            acc.w += fabsf(v.w);
        }
    }
    ((float4*)&g_partial[rb * N_COLS])[col4] = acc;
}

// K2: per-column stats: abs_sum -> lambda, scale, delta, cross; writes center row out[0]
__global__ void k_column_stats(const float* __restrict__ x, float* __restrict__ out) {
    int col = blockIdx.x * blockDim.x + threadIdx.x;    // 0..4095
    float s = 0.f;
    #pragma unroll 16
    for (int rb = 0; rb < ROW_BLOCKS; rb++)
        s += g_partial[rb * N_COLS + col];

    float c     = x[col];                 // x[0] center row
    float upper = c + s;
    float lower = c - s;
    float prod  = lower * upper;
    bool  cross = prod < 0.f;
    bool  pos   = lower >= 0.f;
    float crossf = cross ? 1.f : 0.f;
    float posf   = pos   ? 1.f : 0.f;

    float denom = upper - lower;
    float ratio = (denom != 0.f) ? (upper / denom) : 0.5f;
    float lam   = posf + crossf * ratio;

    float delta  = fmaxf(-lam * lower, (1.f - lam) * upper);
    float center = (delta * 0.5f + lam * c) * crossf + c * posf;

    ((float*)g_scale)[col] = lam * crossf + posf;
    ((float*)g_val)[col]   = delta * 0.5f * crossf;
    ((int*)g_cross)[col]   = cross ? 1 : 0;
    out[col] = center;
}

// K3 (fused output): blockIdx.y < 128 -> gens rows 1..2047 (read x, scale, write);
//                    blockIdx.y >= 128 -> zero tail rows 2048..6143.
// One kernel so the pure-write tail traffic overlaps the gens read latency.
__global__ void k_out(const float* __restrict__ x, float* __restrict__ out) {
    int col4 = blockIdx.x * blockDim.x + threadIdx.x;   // 0..1023
    int cy   = blockIdx.y;                              // 0..383
    float4* o4 = (float4*)out;

    if (cy < ROW_BLOCKS) {
        const float4* x4 = (const float4*)x;
        float4 s = g_scale[col4];                       // loaded once per thread
        int r0 = 1 + cy * ROWS_PER;
        #pragma unroll
        for (int r = 0; r < ROWS_PER; r++) {
            int row = r0 + r;
            if (row < N_TERMS) {
                float4 v = x4[(size_t)row * COL4 + col4];
                v.x *= s.x; v.y *= s.y; v.z *= s.z; v.w *= s.w;
                o4[(size_t)row * COL4 + col4] = v;
            }
        }
    } else {
        int r0 = N_TERMS + (cy - ROW_BLOCKS) * ROWS_PER;
        const float4 z = make_float4(0.f, 0.f, 0.f, 0.f);
        #pragma unroll
        for (int r = 0; r < ROWS_PER; r++)
            o4[(size_t)(r0 + r) * COL4 + col4] = z;
    }
}

// K4: single-block exclusive prefix sum over 4096 cross flags + scatter delta/2
__global__ void k_scatter(float* __restrict__ out) {
    __shared__ int warp_sums[32];
    int t    = threadIdx.x;        // 0..1023, 4 columns each
    int lane = t & 31;
    int wid  = t >> 5;

    int4 cf = g_cross[t];
    int tsum = cf.x + cf.y + cf.z + cf.w;

    int v = tsum;
    #pragma unroll
    for (int o = 1; o < 32; o <<= 1) {
        int n = __shfl_up_sync(0xffffffffu, v, o);
        if (lane >= o) v += n;
    }
    if (lane == 31) warp_sums[wid] = v;
    __syncthreads();
    if (wid == 0) {
        int wv = warp_sums[lane];
        #pragma unroll
        for (int o = 1; o < 32; o <<= 1) {
            int n = __shfl_up_sync(0xffffffffu, wv, o);
            if (lane >= o) wv += n;
        }
        warp_sums[lane] = wv;
    }
    __syncthreads();

    int warp_off = (wid > 0) ? warp_sums[wid - 1] : 0;
    int excl = warp_off + (v - tsum);   // exclusive prefix for this thread's first column

    float4 val = g_val[t];
    int col = t * 4;
    int r = excl;
    if (cf.x) { out[(size_t)(N_TERMS + r) * N_COLS + col + 0] = val.x; r++; }
    if (cf.y) { out[(size_t)(N_TERMS + r) * N_COLS + col + 1] = val.y; r++; }
    if (cf.z) { out[(size_t)(N_TERMS + r) * N_COLS + col + 2] = val.z; r++; }
    if (cf.w) { out[(size_t)(N_TERMS + r) * N_COLS + col + 3] = val.w; }
}

extern "C" void kernel_launch(void* const* d_in, const int* in_sizes, int n_in,
                              void* d_out, int out_size) {
    const float* x = (const float*)d_in[0];
    float* out     = (float*)d_out;

    dim3 g1(COL4 / 256, ROW_BLOCKS);                    // (4, 128)
    k_abs_partial<<<g1, 256>>>(x);
    k_column_stats<<<N_COLS / 256, 256>>>(x, out);
    dim3 g3(COL4 / 256, ROW_BLOCKS + N_COLS / ROWS_PER); // (4, 384)
    k_out<<<g3, 256>>>(x, out);
    k_scatter<<<1, 1024>>>(out);
}

// round 3
// speedup vs baseline: 1.1034x; 1.0697x over previous
#include <cuda_runtime.h>
#include <cuda_bf16.h>

#define N_COLS   4096
#define N_TERMS  2048
#define COL4     (N_COLS / 4)      // 1024 float4 columns
#define ROW_BLOCKS 128
#define ROWS_PER   16              // 128 * 16 = 2048 >= 2047 reduced rows

// ---- scratch (no allocation allowed; device globals) ----
__device__ float  g_partial[ROW_BLOCKS * N_COLS];   // 2 MB partial |x| column sums
__device__ float4 g_scale[COL4];                    // per-column generator scale
__device__ float4 g_val[COL4];                      // per-column delta*0.5*crossf
__device__ int4   g_cross[COL4];                    // per-column crossing flag
__device__ int4   g_row[COL4];                      // per-column target row (or -1)

// K1: partial column reduction of |x| over row chunks (rows 1..2047)
__global__ void k_abs_partial(const float* __restrict__ x) {
    int col4 = blockIdx.x * blockDim.x + threadIdx.x;   // 0..1023
    int rb   = blockIdx.y;
    int r0   = 1 + rb * ROWS_PER;
    const float4* x4 = (const float4*)x;
    float4 acc = make_float4(0.f, 0.f, 0.f, 0.f);
    #pragma unroll
    for (int r = 0; r < ROWS_PER; r++) {
        int row = r0 + r;
        if (row < N_TERMS) {
            float4 v = x4[(size_t)row * COL4 + col4];
            acc.x += fabsf(v.x);
            acc.y += fabsf(v.y);
            acc.z += fabsf(v.z);
            acc.w += fabsf(v.w);
        }
    }
    ((float4*)&g_partial[rb * N_COLS])[col4] = acc;
}

// K2: per-column stats: abs_sum -> lambda, scale, delta, cross; writes center row out[0]
__global__ void k_column_stats(const float* __restrict__ x, float* __restrict__ out) {
    int col = blockIdx.x * blockDim.x + threadIdx.x;    // 0..4095
    float s = 0.f;
    #pragma unroll 16
    for (int rb = 0; rb < ROW_BLOCKS; rb++)
        s += g_partial[rb * N_COLS + col];

    float c     = x[col];                 // x[0] center row
    float upper = c + s;
    float lower = c - s;
    float prod  = lower * upper;
    bool  cross = prod < 0.f;
    bool  pos   = lower >= 0.f;
    float crossf = cross ? 1.f : 0.f;
    float posf   = pos   ? 1.f : 0.f;

    float denom = upper - lower;
    float ratio = (denom != 0.f) ? (upper / denom) : 0.5f;
    float lam   = posf + crossf * ratio;

    float delta  = fmaxf(-lam * lower, (1.f - lam) * upper);
    float center = (delta * 0.5f + lam * c) * crossf + c * posf;

    ((float*)g_scale)[col] = lam * crossf + posf;
    ((float*)g_val)[col]   = delta * 0.5f * crossf;
    ((int*)g_cross)[col]   = cross ? 1 : 0;
    out[col] = center;
}

// K-scan: single block: exclusive prefix sum over 4096 cross flags ->
// per-column target row g_row (or -1 if not crossing). No stores to out.
__global__ void k_scan() {
    __shared__ int warp_sums[32];
    int t    = threadIdx.x;        // 0..1023, 4 columns each
    int lane = t & 31;
    int wid  = t >> 5;

    int4 cf = g_cross[t];
    int tsum = cf.x + cf.y + cf.z + cf.w;

    int v = tsum;
    #pragma unroll
    for (int o = 1; o < 32; o <<= 1) {
        int n = __shfl_up_sync(0xffffffffu, v, o);
        if (lane >= o) v += n;
    }
    if (lane == 31) warp_sums[wid] = v;
    __syncthreads();
    if (wid == 0) {
        int wv = warp_sums[lane];
        #pragma unroll
        for (int o = 1; o < 32; o <<= 1) {
            int n = __shfl_up_sync(0xffffffffu, wv, o);
            if (lane >= o) wv += n;
        }
        warp_sums[lane] = wv;
    }
    __syncthreads();

    int warp_off = (wid > 0) ? warp_sums[wid - 1] : 0;
    int r = warp_off + (v - tsum);   // exclusive prefix for this thread's first column

    int4 tr;
    tr.x = cf.x ? (N_TERMS + r) : -1; r += cf.x;
    tr.y = cf.y ? (N_TERMS + r) : -1; r += cf.y;
    tr.z = cf.z ? (N_TERMS + r) : -1; r += cf.z;
    tr.w = cf.w ? (N_TERMS + r) : -1;
    g_row[t] = tr;
}

// K3 (fused output): blockIdx.y < 128 -> gens rows 1..2047 (read x, scale, write);
//                    blockIdx.y >= 128 -> tail rows 2048..6143: zeros + fused scatter
//                    (write val[col] where g_row[col] falls in this row chunk).
__global__ void k_out(const float* __restrict__ x, float* __restrict__ out) {
    int col4 = blockIdx.x * blockDim.x + threadIdx.x;   // 0..1023
    int cy   = blockIdx.y;                              // 0..383
    float4* o4 = (float4*)out;

    if (cy < ROW_BLOCKS) {
        const float4* x4 = (const float4*)x;
        float4 s = g_scale[col4];                       // loaded once per thread
        int r0 = 1 + cy * ROWS_PER;
        #pragma unroll
        for (int r = 0; r < ROWS_PER; r++) {
            int row = r0 + r;
            if (row < N_TERMS) {
                float4 v = x4[(size_t)row * COL4 + col4];
                v.x *= s.x; v.y *= s.y; v.z *= s.z; v.w *= s.w;
                o4[(size_t)row * COL4 + col4] = v;
            }
        }
    } else {
        int r0 = N_TERMS + (cy - ROW_BLOCKS) * ROWS_PER;
        int4   tr  = g_row[col4];
        float4 val = g_val[col4];
        #pragma unroll
        for (int r = 0; r < ROWS_PER; r++) {
            int row = r0 + r;
            float4 z = make_float4(0.f, 0.f, 0.f, 0.f);
            if (tr.x == row) z.x = val.x;
            if (tr.y == row) z.y = val.y;
            if (tr.z == row) z.z = val.z;
            if (tr.w == row) z.w = val.w;
            o4[(size_t)row * COL4 + col4] = z;
        }
    }
}

extern "C" void kernel_launch(void* const* d_in, const int* in_sizes, int n_in,
                              void* d_out, int out_size) {
    const float* x = (const float*)d_in[0];
    float* out     = (float*)d_out;

    dim3 g1(COL4 / 256, ROW_BLOCKS);                    // (4, 128)
    k_abs_partial<<<g1, 256>>>(x);
    k_column_stats<<<N_COLS / 256, 256>>>(x, out);
    k_scan<<<1, 1024>>>();
    dim3 g3(COL4 / 256, ROW_BLOCKS + N_COLS / ROWS_PER); // (4, 384)
    k_out<<<g3, 256>>>(x, out);
}